// round 9
// baseline (speedup 1.0000x reference)
#include <cuda_runtime.h>
#include <cuda_bf16.h>
#include <math.h>

// ------------------------------------------------------------------
// Problem constants
// ------------------------------------------------------------------
#define TT   4096
#define DD   128
#define HH   512
#define H3   1536
#define EE   256
#define WNW  4
#define NB   128          // persistent CTAs in scan (<=148 SMs -> co-resident)
#define NTH  640          // 20 warps: one per phase-A task

// ------------------------------------------------------------------
// Device scratch (no cudaMalloc allowed anywhere)
// ------------------------------------------------------------------
__device__ float g_xW [TT * H3];                // x@W  + b
__device__ float g_xWa[TT * HH];                // x@Wa + ba
__device__ float g_gwX[(size_t)TT * WNW * H3];  // emb[ids]@Ww + bw
__device__ unsigned char g_mask[TT * WNW];      // canonicalized bool mask
__device__ int   g_any [TT];                    // any(mask) per step
__device__ float g_cw  [WNW * HH];              // per-step c_w exchange buffer
__device__ volatile unsigned int g_arrive[NB];  // poll-all barrier slots

// ------------------------------------------------------------------
// Helpers
// ------------------------------------------------------------------
__device__ __forceinline__ float wsum(float v) {
#pragma unroll
    for (int o = 16; o; o >>= 1) v += __shfl_xor_sync(0xffffffffu, v, o);
    return v;
}
__device__ __forceinline__ float sigf(float x) { return 1.0f / (1.0f + expf(-x)); }

// Atomic-free grid barrier. Each CTA publishes a monotonically increasing
// generation in its own slot; warp 0 of every CTA polls all NB slots and
// min-reduces. Release: data STG -> bar.sync -> threadfence -> flag store.
// Acquire: poll sees min >= target -> threadfence -> bar.sync.
__device__ __forceinline__ void gbar(unsigned int target) {
    __syncthreads();
    if (threadIdx.x < 32) {
        const int lane = threadIdx.x;
        if (lane == 0) {
            __threadfence();
            g_arrive[blockIdx.x] = target;
        }
        unsigned int mn;
        do {
            unsigned int v0 = g_arrive[lane];
            unsigned int v1 = g_arrive[lane + 32];
            unsigned int v2 = g_arrive[lane + 64];
            unsigned int v3 = g_arrive[lane + 96];
            mn = min(min(v0, v1), min(v2, v3));
#pragma unroll
            for (int o = 16; o; o >>= 1)
                mn = min(mn, __shfl_xor_sync(0xffffffffu, mn, o));
        } while (mn < target);
        __threadfence();
    }
    __syncthreads();
}

// ------------------------------------------------------------------
// Barrier state reset (must run every launch: determinism across replays)
// ------------------------------------------------------------------
__global__ void reset_kernel() {
    if (threadIdx.x < NB) g_arrive[threadIdx.x] = 0u;
}

// ------------------------------------------------------------------
// word_mask dtype detection + canonicalization + any() precompute.
// Hypotheses: int32 (0/1 words), float32 (0.0/1.0 words), else uint8.
// ------------------------------------------------------------------
__global__ void mask_kernel(const unsigned char* __restrict__ raw) {
    __shared__ int s_notI32, s_notF32, s_mode;
    int tid = threadIdx.x;
    if (tid == 0) { s_notI32 = 0; s_notF32 = 0; }
    __syncthreads();

    const unsigned int* w = (const unsigned int*)raw;
    int li = 0, lf = 0;
    for (int i = tid; i < TT; i += blockDim.x) {
        unsigned int v = w[i];
        if (v != 0u && v != 1u)          li = 1;
        if (v != 0u && v != 0x3f800000u) lf = 1;
    }
    if (li) atomicOr(&s_notI32, 1);
    if (lf) atomicOr(&s_notF32, 1);
    __syncthreads();
    if (tid == 0) s_mode = (!s_notI32) ? 1 : ((!s_notF32) ? 2 : 0);
    __syncthreads();

    int mode = s_mode;
    for (int i = tid; i < TT * WNW; i += blockDim.x) {
        unsigned char m;
        if (mode == 1)      m = (((const int*)  raw)[i] != 0);
        else if (mode == 2) m = (((const float*)raw)[i] != 0.0f);
        else                m = (raw[i] != 0);
        g_mask[i] = m;
    }
    __syncthreads();
    for (int t = tid; t < TT; t += blockDim.x) {
        g_any[t] = (g_mask[4*t] | g_mask[4*t+1] | g_mask[4*t+2] | g_mask[4*t+3]) ? 1 : 0;
    }
}

// ------------------------------------------------------------------
// GEMM with optional A-row gather and bias:
//   C[M,N] = gather(A)[M,K] @ B[K,N] + bias[N]
// 128x128 tile, BK=16, 256 threads, 8x8 register microtile.
// ------------------------------------------------------------------
#define GBM 128
#define GBN 128
#define GBK 16
__global__ __launch_bounds__(256) void gemm_bias(
    const float* __restrict__ A, const float* __restrict__ B,
    const float* __restrict__ bias, float* __restrict__ C,
    int M, int N, int K, const int* __restrict__ gather)
{
    __shared__ float As[GBK][GBM];
    __shared__ float Bs[GBK][GBN];

    const int tid = threadIdx.x;
    const int bm0 = blockIdx.y * GBM, bn0 = blockIdx.x * GBN;
    const int tx = tid & 15, ty = tid >> 4;

    float acc[8][8];
#pragma unroll
    for (int i = 0; i < 8; i++)
#pragma unroll
        for (int j = 0; j < 8; j++) acc[i][j] = 0.0f;

    int arow[8];
#pragma unroll
    for (int i = 0; i < 8; i++) {
        int m = (tid + i * 256) >> 4;
        int r = bm0 + m;
        arow[i] = gather ? gather[r] : r;
    }

    for (int k0 = 0; k0 < K; k0 += GBK) {
#pragma unroll
        for (int i = 0; i < 8; i++) {
            int lin = tid + i * 256;
            int m = lin >> 4, kk = lin & 15;
            As[kk][m] = A[(size_t)arow[i] * K + k0 + kk];
        }
#pragma unroll
        for (int i = 0; i < 8; i++) {
            int lin = tid + i * 256;
            int kk = lin >> 7, n = lin & 127;
            Bs[kk][n] = B[(size_t)(k0 + kk) * N + bn0 + n];
        }
        __syncthreads();
#pragma unroll
        for (int kk = 0; kk < GBK; kk++) {
            float a[8], bb[8];
#pragma unroll
            for (int i = 0; i < 8; i++) a[i]  = As[kk][ty * 8 + i];
#pragma unroll
            for (int j = 0; j < 8; j++) bb[j] = Bs[kk][tx * 8 + j];
#pragma unroll
            for (int i = 0; i < 8; i++)
#pragma unroll
                for (int j = 0; j < 8; j++) acc[i][j] = fmaf(a[i], bb[j], acc[i][j]);
        }
        __syncthreads();
    }

#pragma unroll
    for (int i = 0; i < 8; i++) {
        int row = bm0 + ty * 8 + i;
#pragma unroll
        for (int j = 0; j < 8; j++) {
            int col = bn0 + tx * 8 + j;
            C[(size_t)row * N + col] = acc[i][j] + bias[col];
        }
    }
}

// ------------------------------------------------------------------
// Persistent scan kernel. 128 CTAs x 640 threads (20 warps). CTA bx owns
// hidden columns j0..j0+3. Each warp owns ONE phase-A triple-dot task and
// holds its 3x512 weight column slice in REGISTERS (48 floats/lane).
//
// warp 0..3  : main gates (i,o,g), vector h_prev, weights from U
// warp 4..19 : word-cell gates (f,i,g), w=(wg-4)>>2, dj=(wg-4)&3, weights Uw
//
// Per step:
//   stage:   sh = h_{t-1}; shs/scs = out rows at word_starts  (smem)
//   phase A: register-weight dots -> s_iog / c_w -> g_cw (+ s_cwown)
//   gbar(2t+1)
//   phase B: alpha[w,dj] = sig(xWa + <c_w[w], Ua[:,dj]>)  (c_w via __ldcg)
//   combine: softmax-weighted cell, write out row t (doubles as Hbuf/Cbuf)
//   gbar(2t+2)   (also protects g_cw reuse)
// ------------------------------------------------------------------
__global__ __launch_bounds__(NTH, 1) void scan_kernel(
    float* __restrict__ out,
    const int* __restrict__ wstarts,
    const float* __restrict__ h0,
    const float* __restrict__ c0,
    const float* __restrict__ U,
    const float* __restrict__ Uw,
    const float* __restrict__ Ua)
{
    __shared__ float sUa[4 * 512];      // Ua columns j0..j0+3
    __shared__ float sh[512];           // h_{t-1}
    __shared__ float shs[4 * 512];      // h at word starts
    __shared__ float scs[4 * 512];      // c at word starts
    __shared__ float s_iog[12];         // sig(i),sig(o),tanh(g) per dj
    __shared__ float s_alpha[16];       // alpha[w*4+dj]
    __shared__ float s_cwown[16];       // c_w[w, j0+dj] (own columns)

    const int tid  = threadIdx.x;
    const int wg   = tid >> 5;
    const int lane = tid & 31;
    const int j0   = blockIdx.x * 4;

    // ---- one-time preload: Ua slice to smem ----
    for (int idx = tid; idx < 4 * 512; idx += NTH) {
        int dj = idx >> 9, k = idx & 511;
        sUa[idx] = Ua[(size_t)k * HH + j0 + dj];
    }

    // ---- one-time preload: per-warp gate weights to registers ----
    // lane l holds k = l + 32*m, m = 0..15, for 3 gate columns.
    float wr0[16], wr1[16], wr2[16];
    {
        int dj; const float* M;
        if (wg < 4) { dj = wg;            M = U;  }
        else        { dj = (wg - 4) & 3;  M = Uw; }
        const int jp = j0 + dj;
#pragma unroll
        for (int m = 0; m < 16; m++) {
            int k = lane + (m << 5);
            wr0[m] = M[(size_t)k * H3 + jp];
            wr1[m] = M[(size_t)k * H3 + 512 + jp];
            wr2[m] = M[(size_t)k * H3 + 1024 + jp];
        }
    }

    float cprev = (tid < 4) ? c0[j0 + tid] : 0.0f;   // register-carried c_{t-1}
    __syncthreads();

    for (int t = 0; t < TT; t++) {
        // ---- stage loads (rows referenced were written in earlier steps;
        //      t==0 uses h0 and zeros, matching Hbuf/Cbuf zero-init) ----
        if (tid < 512) {
            const int k = tid;
            sh[k] = (t == 0) ? h0[k] : out[(size_t)(t - 1) * 1024 + k];
#pragma unroll
            for (int w = 0; w < WNW; w++) {
                int s = wstarts[t * WNW + w];
                size_t base = (size_t)s * 1024;
                shs[w * 512 + k] = (t == 0) ? 0.0f : out[base + k];
                scs[w * 512 + k] = (t == 0) ? 0.0f : out[base + 512 + k];
            }
        }
        __syncthreads();

        // ---- phase A: one register-weight triple-dot per warp ----
        {
            int dj, w = 0; const float* vec; bool isU;
            if (wg < 4) { isU = true;  dj = wg; vec = sh; }
            else { isU = false; int q = wg - 4; w = q >> 2; dj = q & 3;
                   vec = shs + w * 512; }
            const int jp = j0 + dj;

            float add0 = 0.f, add1 = 0.f, add2 = 0.f;
            if (lane == 0) {      // issued early; consumed after wsum
                const float* src = isU ? (g_xW + (size_t)t * H3)
                                       : (g_gwX + (size_t)(t * WNW + w) * H3);
                add0 = src[jp]; add1 = src[512 + jp]; add2 = src[1024 + jp];
            }
            float a0 = 0.f, a1 = 0.f, a2 = 0.f;
#pragma unroll
            for (int m = 0; m < 16; m++) {
                float hv = vec[lane + (m << 5)];
                a0 = fmaf(hv, wr0[m], a0);
                a1 = fmaf(hv, wr1[m], a1);
                a2 = fmaf(hv, wr2[m], a2);
            }
            a0 = wsum(a0); a1 = wsum(a1); a2 = wsum(a2);
            if (lane == 0) {
                if (isU) {
                    s_iog[dj * 3 + 0] = sigf(add0 + a0);   // i (sigmoided)
                    s_iog[dj * 3 + 1] = sigf(add1 + a1);   // o
                    s_iog[dj * 3 + 2] = tanhf(add2 + a2);  // g (tanh'd)
                } else {
                    // gw split order: f, i, g
                    float cwv = sigf(add0 + a0) * scs[w * 512 + jp]
                              + sigf(add1 + a1) * tanhf(add2 + a2);
                    g_cw[w * 512 + jp] = cwv;
                    s_cwown[w * 4 + dj] = cwv;
                }
            }
        }
        gbar(2u * t + 1u);

        // ---- phase B: alpha dots, c_w streamed from L2 (rewritten data) ----
        if (wg < 16) {
            const int w = wg >> 2, dj = wg & 3;
            const int jp = j0 + dj;
            float add = (lane == 0) ? g_xWa[(size_t)t * HH + jp] : 0.f;
            const float* cv = g_cw + w * 512;
            const float* ua = sUa + dj * 512;
            float a = 0.f;
#pragma unroll
            for (int m = 0; m < 16; m++) {
                int k = lane + (m << 5);
                a = fmaf(__ldcg(cv + k), ua[k], a);
            }
            a = wsum(a);
            if (lane == 0) s_alpha[wg] = sigf(add + a);
        }
        __syncthreads();

        // ---- final combine: 4 threads, one per owned column ----
        if (tid < 4) {
            const int dj = tid, jp = j0 + dj;
            float ig = s_iog[dj * 3 + 0];
            float og = s_iog[dj * 3 + 1];
            float gg = s_iog[dj * 3 + 2];
            float e0 = expf(ig);
            float se = e0, num = e0 * gg;
#pragma unroll
            for (int w = 0; w < WNW; w++) {
                if (g_mask[t * WNW + w]) {
                    float ew = expf(s_alpha[w * 4 + dj]);
                    se += ew;
                    num = fmaf(ew, s_cwown[w * 4 + dj], num);
                }
            }
            float c1 = g_any[t] ? (num / se)
                                : ((1.0f - ig) * cprev + ig * gg);
            float h1 = og * tanhf(c1);
            out[(size_t)t * 1024 + jp]       = h1;
            out[(size_t)t * 1024 + 512 + jp] = c1;
            cprev = c1;
        }
        gbar(2u * t + 2u);   // publish out[t] + protect g_cw reuse
    }
}

// ------------------------------------------------------------------
// Launch. Input order (metadata): x, word_ids, word_starts, word_mask,
// h0, c0, emb, W, U, b, Wa, Ua, ba, Ww, Uw, bw.  Output: [T, 2H] f32.
// ------------------------------------------------------------------
extern "C" void kernel_launch(void* const* d_in, const int* in_sizes, int n_in,
                              void* d_out, int out_size)
{
    const float*         x        = (const float*)d_in[0];
    const int*           word_ids = (const int*)  d_in[1];
    const int*           wstarts  = (const int*)  d_in[2];
    const unsigned char* mraw     = (const unsigned char*)d_in[3];
    const float*         h0       = (const float*)d_in[4];
    const float*         c0       = (const float*)d_in[5];
    const float*         emb      = (const float*)d_in[6];
    const float*         W        = (const float*)d_in[7];
    const float*         U        = (const float*)d_in[8];
    const float*         b        = (const float*)d_in[9];
    const float*         Wa       = (const float*)d_in[10];
    const float*         Ua       = (const float*)d_in[11];
    const float*         ba       = (const float*)d_in[12];
    const float*         Ww       = (const float*)d_in[13];
    const float*         Uw       = (const float*)d_in[14];
    const float*         bw       = (const float*)d_in[15];
    float*               out      = (float*)d_out;

    (void)in_sizes; (void)n_in; (void)out_size;

    void *pxW = nullptr, *pxWa = nullptr, *pgwX = nullptr;
    cudaGetSymbolAddress(&pxW,  g_xW);
    cudaGetSymbolAddress(&pxWa, g_xWa);
    cudaGetSymbolAddress(&pgwX, g_gwX);

    reset_kernel<<<1, 128>>>();
    mask_kernel<<<1, 1024>>>(mraw);

    // xW  = x @ W  + b    : [4096,128]@[128,1536]
    gemm_bias<<<dim3(H3 / GBN, TT / GBM), 256>>>(
        x, W, b, (float*)pxW, TT, H3, DD, nullptr);
    // xWa = x @ Wa + ba   : [4096,128]@[128,512]
    gemm_bias<<<dim3(HH / GBN, TT / GBM), 256>>>(
        x, Wa, ba, (float*)pxWa, TT, HH, DD, nullptr);
    // gwX = emb[word_ids] @ Ww + bw : [16384,256]@[256,1536]
    gemm_bias<<<dim3(H3 / GBN, (TT * WNW) / GBM), 256>>>(
        emb, Ww, bw, (float*)pgwX, TT * WNW, H3, EE, word_ids);

    scan_kernel<<<NB, NTH>>>(out, wstarts, h0, c0, U, Uw, Ua);
}

// round 10
// speedup vs baseline: 2.0361x; 2.0361x over previous
#include <cuda_runtime.h>
#include <cuda_bf16.h>
#include <math.h>

// ------------------------------------------------------------------
// Problem constants
// ------------------------------------------------------------------
#define TT   4096
#define DD   128
#define HH   512
#define H3   1536
#define EE   256
#define WNW  4
#define NB   128          // persistent CTAs in scan (<=148 SMs -> co-resident)
#define NTH  640          // 20 warps: one per phase-A task

// ------------------------------------------------------------------
// Device scratch (no cudaMalloc allowed anywhere)
// ------------------------------------------------------------------
__device__ float g_xW [TT * H3];                // x@W  + b
__device__ float g_xWa[TT * HH];                // x@Wa + ba
__device__ float g_gwX[(size_t)TT * WNW * H3];  // emb[ids]@Ww + bw
__device__ unsigned char g_mask[TT * WNW];      // canonicalized bool mask
__device__ int   g_any [TT];                    // any(mask) per step
__device__ float g_cw  [WNW * HH];              // per-step c_w exchange buffer
__device__ unsigned int          g_count;       // barrier arrival counter
__device__ volatile unsigned int g_gen;         // barrier generation flag

// ------------------------------------------------------------------
// Helpers
// ------------------------------------------------------------------
__device__ __forceinline__ float wsum(float v) {
#pragma unroll
    for (int o = 16; o; o >>= 1) v += __shfl_xor_sync(0xffffffffu, v, o);
    return v;
}
__device__ __forceinline__ float sigf(float x) { return 1.0f / (1.0f + expf(-x)); }

// Canonical grid barrier (cooperative-groups pattern): one atomicAdd arrival
// per CTA, 128 single-thread spinners on ONE flag word. Spin traffic =
// 128 same-line reads per poll round (vs 16K for poll-all -> R8 regression).
__device__ __forceinline__ void gbar(unsigned int target) {
    __syncthreads();
    if (threadIdx.x == 0) {
        __threadfence();
        unsigned int old = atomicAdd(&g_count, 1u);
        if (old == NB - 1u) {
            atomicExch(&g_count, 0u);
            __threadfence();
            g_gen = target;                  // release
        } else {
            while (g_gen < target) { }       // single-thread L2 spin
            __threadfence();                 // acquire
        }
    }
    __syncthreads();
}

// ------------------------------------------------------------------
// Barrier state reset (must run every launch: determinism across replays)
// ------------------------------------------------------------------
__global__ void reset_kernel() {
    g_count = 0u;
    g_gen   = 0u;
}

// ------------------------------------------------------------------
// word_mask dtype detection + canonicalization + any() precompute.
// Hypotheses: int32 (0/1 words), float32 (0.0/1.0 words), else uint8.
// ------------------------------------------------------------------
__global__ void mask_kernel(const unsigned char* __restrict__ raw) {
    __shared__ int s_notI32, s_notF32, s_mode;
    int tid = threadIdx.x;
    if (tid == 0) { s_notI32 = 0; s_notF32 = 0; }
    __syncthreads();

    const unsigned int* w = (const unsigned int*)raw;
    int li = 0, lf = 0;
    for (int i = tid; i < TT; i += blockDim.x) {
        unsigned int v = w[i];
        if (v != 0u && v != 1u)          li = 1;
        if (v != 0u && v != 0x3f800000u) lf = 1;
    }
    if (li) atomicOr(&s_notI32, 1);
    if (lf) atomicOr(&s_notF32, 1);
    __syncthreads();
    if (tid == 0) s_mode = (!s_notI32) ? 1 : ((!s_notF32) ? 2 : 0);
    __syncthreads();

    int mode = s_mode;
    for (int i = tid; i < TT * WNW; i += blockDim.x) {
        unsigned char m;
        if (mode == 1)      m = (((const int*)  raw)[i] != 0);
        else if (mode == 2) m = (((const float*)raw)[i] != 0.0f);
        else                m = (raw[i] != 0);
        g_mask[i] = m;
    }
    __syncthreads();
    for (int t = tid; t < TT; t += blockDim.x) {
        g_any[t] = (g_mask[4*t] | g_mask[4*t+1] | g_mask[4*t+2] | g_mask[4*t+3]) ? 1 : 0;
    }
}

// ------------------------------------------------------------------
// GEMM with optional A-row gather and bias:
//   C[M,N] = gather(A)[M,K] @ B[K,N] + bias[N]
// 128x128 tile, BK=16, 256 threads, 8x8 register microtile.
// ------------------------------------------------------------------
#define GBM 128
#define GBN 128
#define GBK 16
__global__ __launch_bounds__(256) void gemm_bias(
    const float* __restrict__ A, const float* __restrict__ B,
    const float* __restrict__ bias, float* __restrict__ C,
    int M, int N, int K, const int* __restrict__ gather)
{
    __shared__ float As[GBK][GBM];
    __shared__ float Bs[GBK][GBN];

    const int tid = threadIdx.x;
    const int bm0 = blockIdx.y * GBM, bn0 = blockIdx.x * GBN;
    const int tx = tid & 15, ty = tid >> 4;

    float acc[8][8];
#pragma unroll
    for (int i = 0; i < 8; i++)
#pragma unroll
        for (int j = 0; j < 8; j++) acc[i][j] = 0.0f;

    int arow[8];
#pragma unroll
    for (int i = 0; i < 8; i++) {
        int m = (tid + i * 256) >> 4;
        int r = bm0 + m;
        arow[i] = gather ? gather[r] : r;
    }

    for (int k0 = 0; k0 < K; k0 += GBK) {
#pragma unroll
        for (int i = 0; i < 8; i++) {
            int lin = tid + i * 256;
            int m = lin >> 4, kk = lin & 15;
            As[kk][m] = A[(size_t)arow[i] * K + k0 + kk];
        }
#pragma unroll
        for (int i = 0; i < 8; i++) {
            int lin = tid + i * 256;
            int kk = lin >> 7, n = lin & 127;
            Bs[kk][n] = B[(size_t)(k0 + kk) * N + bn0 + n];
        }
        __syncthreads();
#pragma unroll
        for (int kk = 0; kk < GBK; kk++) {
            float a[8], bb[8];
#pragma unroll
            for (int i = 0; i < 8; i++) a[i]  = As[kk][ty * 8 + i];
#pragma unroll
            for (int j = 0; j < 8; j++) bb[j] = Bs[kk][tx * 8 + j];
#pragma unroll
            for (int i = 0; i < 8; i++)
#pragma unroll
                for (int j = 0; j < 8; j++) acc[i][j] = fmaf(a[i], bb[j], acc[i][j]);
        }
        __syncthreads();
    }

#pragma unroll
    for (int i = 0; i < 8; i++) {
        int row = bm0 + ty * 8 + i;
#pragma unroll
        for (int j = 0; j < 8; j++) {
            int col = bn0 + tx * 8 + j;
            C[(size_t)row * N + col] = acc[i][j] + bias[col];
        }
    }
}

// ------------------------------------------------------------------
// Persistent scan kernel. 128 CTAs x 640 threads (20 warps). CTA bx owns
// hidden columns j0..j0+3. Each warp owns ONE phase-A triple-dot task and
// holds its 3x512 recurrent-weight column slice in REGISTERS (48 f/lane).
// h-vectors are streamed DIRECTLY from out[] (no smem staging): rows of
// out are write-once-then-read, so default L1 caching is safe, and L1 is
// flushed at every launch (graph replays included).
//
// warp 0..3  : main gates (i,o,g), vector h_{t-1},        weights U
// warp 4..19 : word-cell gates (f,i,g), w,dj decode,      weights Uw
//
// Per step:
//   phase A: register-weight dots -> s_iog / c_w -> g_cw (+ s_cwown)
//   gbar(2t+1)
//   phase B: alpha[w,dj] = sig(xWa + <c_w[w], Ua[:,dj]>)  (c_w via __ldcg)
//            warp 16 prefetches mask/any for the combine
//   combine: softmax-weighted cell, write out row t (doubles as Hbuf/Cbuf)
//   gbar(2t+2)   (publishes out[t]; protects g_cw reuse)
// ------------------------------------------------------------------
__global__ __launch_bounds__(NTH, 1) void scan_kernel(
    float* __restrict__ out,
    const int* __restrict__ wstarts,
    const float* __restrict__ h0,
    const float* __restrict__ c0,
    const float* __restrict__ U,
    const float* __restrict__ Uw,
    const float* __restrict__ Ua)
{
    __shared__ float sUa[4 * 512];      // Ua columns j0..j0+3
    __shared__ float s_iog[12];         // sig(i),sig(o),tanh(g) per dj
    __shared__ float s_alpha[16];       // alpha[w*4+dj]
    __shared__ float s_cwown[16];       // c_w[w, j0+dj] (own columns)
    __shared__ int   s_mask4[4];        // mask[t, 0..3]
    __shared__ int   s_anyt;            // any(mask[t])

    const int tid  = threadIdx.x;
    const int wg   = tid >> 5;
    const int lane = tid & 31;
    const int j0   = blockIdx.x * 4;

    // ---- one-time preload: Ua slice to smem ----
    for (int idx = tid; idx < 4 * 512; idx += NTH) {
        int dj = idx >> 9, k = idx & 511;
        sUa[idx] = Ua[(size_t)k * HH + j0 + dj];
    }

    // ---- one-time preload: per-warp gate weights to registers ----
    // lane l holds k = l + 32*m, m = 0..15, for this warp's 3 gate columns.
    const bool isU = (wg < 4);
    const int  dj  = isU ? wg : ((wg - 4) & 3);
    const int  wrd = isU ? 0  : ((wg - 4) >> 2);
    const int  jp  = j0 + dj;
    float wr0[16], wr1[16], wr2[16];
    {
        const float* M = isU ? U : Uw;
#pragma unroll
        for (int m = 0; m < 16; m++) {
            int k = lane + (m << 5);
            wr0[m] = M[(size_t)k * H3 + jp];
            wr1[m] = M[(size_t)k * H3 + 512 + jp];
            wr2[m] = M[(size_t)k * H3 + 1024 + jp];
        }
    }

    float cprev = (tid < 4) ? c0[j0 + tid] : 0.0f;   // register-carried c_{t-1}
    __syncthreads();

    for (int t = 0; t < TT; t++) {
        // ---- phase A: one register-weight triple-dot per warp, vector
        //      streamed straight from out[] (or h0 / zeros at t==0) ----
        {
            const float* vec;
            float csv = 0.0f;                    // c at word start (own col)
            bool  dovec = true;
            if (isU) {
                vec = (t == 0) ? h0 : (out + (size_t)(t - 1) * 1024);
            } else {
                int s = __ldg(&wstarts[t * WNW + wrd]);
                vec = out + (size_t)s * 1024;
                if (t == 0) dovec = false;       // Hbuf/Cbuf are zeros at t=0
                else if (lane == 0) csv = out[(size_t)s * 1024 + 512 + jp];
            }

            float add0 = 0.f, add1 = 0.f, add2 = 0.f;
            if (lane == 0) {                     // issued early, used after wsum
                const float* src = isU ? (g_xW + (size_t)t * H3)
                                       : (g_gwX + (size_t)(t * WNW + wrd) * H3);
                add0 = __ldg(src + jp);
                add1 = __ldg(src + 512 + jp);
                add2 = __ldg(src + 1024 + jp);
            }

            float a0 = 0.f, a1 = 0.f, a2 = 0.f;
            if (dovec) {
#pragma unroll
                for (int m = 0; m < 16; m++) {
                    float hv = vec[lane + (m << 5)];
                    a0 = fmaf(hv, wr0[m], a0);
                    a1 = fmaf(hv, wr1[m], a1);
                    a2 = fmaf(hv, wr2[m], a2);
                }
            }
            a0 = wsum(a0); a1 = wsum(a1); a2 = wsum(a2);
            if (lane == 0) {
                if (isU) {
                    s_iog[dj * 3 + 0] = sigf(add0 + a0);   // i (sigmoided)
                    s_iog[dj * 3 + 1] = sigf(add1 + a1);   // o
                    s_iog[dj * 3 + 2] = tanhf(add2 + a2);  // g (tanh'd)
                } else {
                    // gw split order: f, i, g
                    float cwv = sigf(add0 + a0) * csv
                              + sigf(add1 + a1) * tanhf(add2 + a2);
                    g_cw[wrd * 512 + jp] = cwv;
                    s_cwown[wrd * 4 + dj] = cwv;
                }
            }
        }
        gbar(2u * t + 1u);

        // ---- phase B: alpha dots, c_w streamed from L2 (rewritten data) ----
        if (wg < 16) {
            const int w2 = wg >> 2, dj2 = wg & 3;
            const int jp2 = j0 + dj2;
            float add = (lane == 0) ? __ldg(&g_xWa[(size_t)t * HH + jp2]) : 0.f;
            const float* cv = g_cw + w2 * 512;
            const float* ua = sUa + dj2 * 512;
            float a = 0.f;
#pragma unroll
            for (int m = 0; m < 16; m++) {
                int k = lane + (m << 5);
                a = fmaf(__ldcg(cv + k), ua[k], a);
            }
            a = wsum(a);
            if (lane == 0) s_alpha[wg] = sigf(add + a);
        } else if (wg == 16) {
            if (lane < 4) s_mask4[lane] = (int)g_mask[t * WNW + lane];
            if (lane == 4) s_anyt = g_any[t];
        }
        __syncthreads();

        // ---- final combine: 4 threads, one per owned column ----
        if (tid < 4) {
            const int dc = tid, jc = j0 + dc;
            float ig = s_iog[dc * 3 + 0];
            float og = s_iog[dc * 3 + 1];
            float gg = s_iog[dc * 3 + 2];
            float e0 = expf(ig);
            float se = e0, num = e0 * gg;
#pragma unroll
            for (int w = 0; w < WNW; w++) {
                if (s_mask4[w]) {
                    float ew = expf(s_alpha[w * 4 + dc]);
                    se += ew;
                    num = fmaf(ew, s_cwown[w * 4 + dc], num);
                }
            }
            float c1 = s_anyt ? (num / se)
                              : ((1.0f - ig) * cprev + ig * gg);
            float h1 = og * tanhf(c1);
            out[(size_t)t * 1024 + jc]       = h1;
            out[(size_t)t * 1024 + 512 + jc] = c1;
            cprev = c1;
        }
        gbar(2u * t + 2u);   // publish out[t] + protect g_cw reuse
    }
}

// ------------------------------------------------------------------
// Launch. Input order (metadata): x, word_ids, word_starts, word_mask,
// h0, c0, emb, W, U, b, Wa, Ua, ba, Ww, Uw, bw.  Output: [T, 2H] f32.
// ------------------------------------------------------------------
extern "C" void kernel_launch(void* const* d_in, const int* in_sizes, int n_in,
                              void* d_out, int out_size)
{
    const float*         x        = (const float*)d_in[0];
    const int*           word_ids = (const int*)  d_in[1];
    const int*           wstarts  = (const int*)  d_in[2];
    const unsigned char* mraw     = (const unsigned char*)d_in[3];
    const float*         h0       = (const float*)d_in[4];
    const float*         c0       = (const float*)d_in[5];
    const float*         emb      = (const float*)d_in[6];
    const float*         W        = (const float*)d_in[7];
    const float*         U        = (const float*)d_in[8];
    const float*         b        = (const float*)d_in[9];
    const float*         Wa       = (const float*)d_in[10];
    const float*         Ua       = (const float*)d_in[11];
    const float*         ba       = (const float*)d_in[12];
    const float*         Ww       = (const float*)d_in[13];
    const float*         Uw       = (const float*)d_in[14];
    const float*         bw       = (const float*)d_in[15];
    float*               out      = (float*)d_out;

    (void)in_sizes; (void)n_in; (void)out_size;

    void *pxW = nullptr, *pxWa = nullptr, *pgwX = nullptr;
    cudaGetSymbolAddress(&pxW,  g_xW);
    cudaGetSymbolAddress(&pxWa, g_xWa);
    cudaGetSymbolAddress(&pgwX, g_gwX);

    reset_kernel<<<1, 32>>>();
    mask_kernel<<<1, 1024>>>(mraw);

    // xW  = x @ W  + b    : [4096,128]@[128,1536]
    gemm_bias<<<dim3(H3 / GBN, TT / GBM), 256>>>(
        x, W, b, (float*)pxW, TT, H3, DD, nullptr);
    // xWa = x @ Wa + ba   : [4096,128]@[128,512]
    gemm_bias<<<dim3(HH / GBN, TT / GBM), 256>>>(
        x, Wa, ba, (float*)pxWa, TT, HH, DD, nullptr);
    // gwX = emb[word_ids] @ Ww + bw : [16384,256]@[256,1536]
    gemm_bias<<<dim3(H3 / GBN, (TT * WNW) / GBM), 256>>>(
        emb, Ww, bw, (float*)pgwX, TT * WNW, H3, EE, word_ids);

    scan_kernel<<<NB, NTH>>>(out, wstarts, h0, c0, U, Uw, Ua);
}